// round 1
// baseline (speedup 1.0000x reference)
#include <cuda_runtime.h>
#include <cstdint>

// Problem constants
#define PB 2
#define PS 2048
#define PE 1024
#define PH 16
#define PHD 64
#define MROWS (PB * PS * PH)   // 65536 rows of the [M,64] view of x
#define PAD 65                 // smem row pad (floats) to dodge bank conflicts

// Scratch (allocation-free rule: __device__ globals)
__device__ float g_Q[(size_t)PB * PH * PS * PHD];
__device__ float g_K[(size_t)PB * PH * PS * PHD];
__device__ float g_V[(size_t)PB * PH * PS * PHD];
__device__ float g_Y[(size_t)PB * PS * PE];

// ---------------------------------------------------------------------------
// Kernel 1: fused QKV projection.
// x viewed as [MROWS, 64] (row = (b*S+s)*H + h). Q/K/V row-major [B,H,S,HD].
// q_e = sum_d x_d * W[e,d] + b_e  (torch Linear convention)
// ---------------------------------------------------------------------------
__global__ __launch_bounds__(256) void qkv_kernel(
    const float* __restrict__ x,
    const float* __restrict__ Wq, const float* __restrict__ bq,
    const float* __restrict__ Wk, const float* __restrict__ bk,
    const float* __restrict__ Wv, const float* __restrict__ bv) {
  extern __shared__ float sm[];
  float* Xs = sm;                 // 64*PAD
  float* Aq = Xs + 64 * PAD;
  float* Ak = Aq + 64 * PAD;
  float* Av = Ak + 64 * PAD;
  const int tid = threadIdx.x;
  const int rowbase = blockIdx.x * 64;

  for (int idx = tid; idx < 64 * 64; idx += 256) {
    int r = idx >> 6, d = idx & 63;
    Xs[r * PAD + d] = x[(size_t)(rowbase + r) * 64 + d];
    Aq[r * PAD + d] = Wq[idx];
    Ak[r * PAD + d] = Wk[idx];
    Av[r * PAD + d] = Wv[idx];
  }
  __syncthreads();

  const int ty = tid >> 4, tx = tid & 15;
  float aq[4][4] = {}, ak[4][4] = {}, av[4][4] = {};
  for (int d = 0; d < 64; d++) {
    float xv[4], wq[4], wk[4], wv[4];
#pragma unroll
    for (int i = 0; i < 4; i++) xv[i] = Xs[(4 * ty + i) * PAD + d];
#pragma unroll
    for (int j = 0; j < 4; j++) {
      wq[j] = Aq[(4 * tx + j) * PAD + d];
      wk[j] = Ak[(4 * tx + j) * PAD + d];
      wv[j] = Av[(4 * tx + j) * PAD + d];
    }
#pragma unroll
    for (int i = 0; i < 4; i++)
#pragma unroll
      for (int j = 0; j < 4; j++) {
        aq[i][j] += xv[i] * wq[j];
        ak[i][j] += xv[i] * wk[j];
        av[i][j] += xv[i] * wv[j];
      }
  }

#pragma unroll
  for (int i = 0; i < 4; i++) {
    int row = rowbase + 4 * ty + i;
    int b = row / (PS * PH);
    int rem = row - b * (PS * PH);
    int s = rem / PH;
    int h = rem - s * PH;
    size_t base = ((size_t)(b * PH + h) * PS + s) * PHD + 4 * tx;
#pragma unroll
    for (int j = 0; j < 4; j++) {
      g_Q[base + j] = aq[i][j] + bq[4 * tx + j];
      g_K[base + j] = ak[i][j] + bk[4 * tx + j];
      g_V[base + j] = av[i][j] + bv[4 * tx + j];
    }
  }
}

// ---------------------------------------------------------------------------
// Kernel 2: causal flash attention, fp32. One block = one (b,h) x 64-query tile.
// Online softmax, 4x4 microtiles, P staged through smem for the PV GEMM.
// Writes attention output directly into [B,S,E] layout for the proj GEMM.
// ---------------------------------------------------------------------------
__global__ __launch_bounds__(256) void attn_kernel() {
  extern __shared__ float sm[];
  float* Qs = sm;                 // [64][PAD]
  float* Ks = Qs + 64 * PAD;
  float* Vs = Ks + 64 * PAD;
  float* Ps = Vs + 64 * PAD;
  const int tid = threadIdx.x;
  const int ty = tid >> 4, tx = tid & 15;
  const int bh = blockIdx.y;
  const int qi = (PS / 64 - 1) - blockIdx.x;  // big tiles scheduled first

  const float* Qg = g_Q + ((size_t)bh * PS + (size_t)qi * 64) * PHD;
  for (int idx = tid; idx < 64 * 64; idx += 256) {
    int r = idx >> 6, d = idx & 63;
    Qs[r * PAD + d] = Qg[idx] * 0.125f;  // 1/sqrt(64) folded into Q
  }

  float m[4], l[4], O[4][4];
#pragma unroll
  for (int i = 0; i < 4; i++) {
    m[i] = -1e30f;
    l[i] = 0.f;
#pragma unroll
    for (int j = 0; j < 4; j++) O[i][j] = 0.f;
  }

  for (int j = 0; j <= qi; j++) {
    __syncthreads();  // prev iteration done with Ks/Vs/Ps (also covers Qs load)
    const float* Kg = g_K + ((size_t)bh * PS + (size_t)j * 64) * PHD;
    const float* Vg = g_V + ((size_t)bh * PS + (size_t)j * 64) * PHD;
    for (int idx = tid; idx < 64 * 64; idx += 256) {
      int r = idx >> 6, d = idx & 63;
      Ks[r * PAD + d] = Kg[idx];
      Vs[r * PAD + d] = Vg[idx];
    }
    __syncthreads();

    float s[4][4] = {};
    for (int d = 0; d < 64; d++) {
      float qv[4], kv[4];
#pragma unroll
      for (int i = 0; i < 4; i++) qv[i] = Qs[(4 * ty + i) * PAD + d];
#pragma unroll
      for (int jj = 0; jj < 4; jj++) kv[jj] = Ks[(4 * tx + jj) * PAD + d];
#pragma unroll
      for (int i = 0; i < 4; i++)
#pragma unroll
        for (int jj = 0; jj < 4; jj++) s[i][jj] += qv[i] * kv[jj];
    }

    if (j == qi) {  // diagonal tile: causal mask (key offset > query offset)
#pragma unroll
      for (int i = 0; i < 4; i++)
#pragma unroll
        for (int jj = 0; jj < 4; jj++)
          if (4 * tx + jj > 4 * ty + i) s[i][jj] = -1e30f;
    }

#pragma unroll
    for (int i = 0; i < 4; i++) {
      float tmax = fmaxf(fmaxf(s[i][0], s[i][1]), fmaxf(s[i][2], s[i][3]));
#pragma unroll
      for (int o = 8; o >= 1; o >>= 1)
        tmax = fmaxf(tmax, __shfl_xor_sync(0xffffffffu, tmax, o));
      float nm = fmaxf(m[i], tmax);
      float sc = __expf(m[i] - nm);
      m[i] = nm;
      float rs = 0.f;
#pragma unroll
      for (int jj = 0; jj < 4; jj++) {
        float p = __expf(s[i][jj] - nm);
        s[i][jj] = p;
        rs += p;
      }
#pragma unroll
      for (int o = 8; o >= 1; o >>= 1) rs += __shfl_xor_sync(0xffffffffu, rs, o);
      l[i] = l[i] * sc + rs;
#pragma unroll
      for (int jj = 0; jj < 4; jj++) O[i][jj] *= sc;
#pragma unroll
      for (int jj = 0; jj < 4; jj++)
        Ps[(4 * ty + i) * PAD + 4 * tx + jj] = s[i][jj];
    }
    __syncthreads();

    for (int k = 0; k < 64; k++) {
      float pv[4], vv[4];
#pragma unroll
      for (int i = 0; i < 4; i++) pv[i] = Ps[(4 * ty + i) * PAD + k];
#pragma unroll
      for (int jj = 0; jj < 4; jj++) vv[jj] = Vs[k * PAD + 4 * tx + jj];
#pragma unroll
      for (int i = 0; i < 4; i++)
#pragma unroll
        for (int jj = 0; jj < 4; jj++) O[i][jj] += pv[i] * vv[jj];
    }
  }

  const int b = bh / PH, h = bh - b * PH;
#pragma unroll
  for (int i = 0; i < 4; i++) {
    int srow = qi * 64 + 4 * ty + i;
    float inv = 1.f / l[i];
    size_t base = ((size_t)b * PS + srow) * PE + h * PHD + 4 * tx;
#pragma unroll
    for (int jj = 0; jj < 4; jj++) g_Y[base + jj] = O[i][jj] * inv;
  }
}

// ---------------------------------------------------------------------------
// Kernel 3: output projection. out[M=4096, E] = Y @ Wp^T + bp
// ---------------------------------------------------------------------------
__global__ __launch_bounds__(256) void proj_kernel(
    const float* __restrict__ W, const float* __restrict__ bias,
    float* __restrict__ out) {
  __shared__ float Ys[64 * PAD];
  __shared__ float Ws[64 * PAD];
  const int tid = threadIdx.x;
  const int ty = tid >> 4, tx = tid & 15;
  const int bm = blockIdx.y, bn = blockIdx.x;

  float acc[4][4] = {};
  for (int kt = 0; kt < PE / 64; kt++) {
    __syncthreads();
    for (int idx = tid; idx < 64 * 64; idx += 256) {
      int r = idx >> 6, d = idx & 63;
      Ys[r * PAD + d] = g_Y[(size_t)(bm * 64 + r) * PE + kt * 64 + d];
      Ws[r * PAD + d] = W[(size_t)(bn * 64 + r) * PE + kt * 64 + d];
    }
    __syncthreads();
    for (int d = 0; d < 64; d++) {
      float yv[4], wv[4];
#pragma unroll
      for (int i = 0; i < 4; i++) yv[i] = Ys[(4 * ty + i) * PAD + d];
#pragma unroll
      for (int j = 0; j < 4; j++) wv[j] = Ws[(4 * tx + j) * PAD + d];
#pragma unroll
      for (int i = 0; i < 4; i++)
#pragma unroll
        for (int j = 0; j < 4; j++) acc[i][j] += yv[i] * wv[j];
    }
  }

#pragma unroll
  for (int i = 0; i < 4; i++)
#pragma unroll
    for (int j = 0; j < 4; j++)
      out[(size_t)(bm * 64 + 4 * ty + i) * PE + bn * 64 + 4 * tx + j] =
          acc[i][j] + bias[bn * 64 + 4 * tx + j];
}

// ---------------------------------------------------------------------------
extern "C" void kernel_launch(void* const* d_in, const int* in_sizes, int n_in,
                              void* d_out, int out_size) {
  const float* x  = (const float*)d_in[0];
  const float* Wq = (const float*)d_in[1];
  const float* bq = (const float*)d_in[2];
  const float* Wk = (const float*)d_in[3];
  const float* bk = (const float*)d_in[4];
  const float* Wv = (const float*)d_in[5];
  const float* bv = (const float*)d_in[6];
  const float* Wp = (const float*)d_in[7];
  const float* bp = (const float*)d_in[8];
  float* out = (float*)d_out;

  const int smem_big = 4 * 64 * PAD * (int)sizeof(float);  // 66,560 B
  // Idempotent, capture-safe (not a stream op); done every call (no static guards).
  cudaFuncSetAttribute(qkv_kernel, cudaFuncAttributeMaxDynamicSharedMemorySize, smem_big);
  cudaFuncSetAttribute(attn_kernel, cudaFuncAttributeMaxDynamicSharedMemorySize, smem_big);

  qkv_kernel<<<MROWS / 64, 256, smem_big>>>(x, Wq, bq, Wk, bk, Wv, bv);
  attn_kernel<<<dim3(PS / 64, PB * PH), 256, smem_big>>>();
  proj_kernel<<<dim3(PE / 64, (PB * PS) / 64), 256>>>(Wp, bp, out);
}

// round 2
// speedup vs baseline: 4.4841x; 4.4841x over previous
#include <cuda_runtime.h>
#include <cstdint>

#define PB 2
#define PS 2048
#define PE 1024
#define PH 16
#define PHD 64
#define MROWS (PB * PS * PH)
#define PAD 68   // 68 mod 32 == 4 -> fragment pattern (g*PAD + t) maps to 4g+t, injective over g<8,t<4

__device__ float g_Q[(size_t)PB * PH * PS * PHD];
__device__ float g_K[(size_t)PB * PH * PS * PHD];
__device__ float g_V[(size_t)PB * PH * PS * PHD];
__device__ float g_Y[(size_t)PB * PS * PE];

__device__ __forceinline__ uint32_t f2tf(float x) {
  uint32_t u;
  asm("cvt.rna.tf32.f32 %0, %1;" : "=r"(u) : "f"(x));
  return u;
}

__device__ __forceinline__ void mma_tf32(float c[4], uint32_t a0, uint32_t a1,
                                         uint32_t a2, uint32_t a3, uint32_t b0,
                                         uint32_t b1) {
  asm volatile(
      "mma.sync.aligned.m16n8k8.row.col.f32.tf32.tf32.f32 "
      "{%0,%1,%2,%3}, {%4,%5,%6,%7}, {%8,%9}, {%0,%1,%2,%3};"
      : "+f"(c[0]), "+f"(c[1]), "+f"(c[2]), "+f"(c[3])
      : "r"(a0), "r"(a1), "r"(a2), "r"(a3), "r"(b0), "r"(b1));
}

// ---------------------------------------------------------------------------
// Kernel 1: fused QKV projection (tf32 mma).
// x viewed as [MROWS,64]; W row-major [e][d]; out = x @ W^T + b.
// Block: 64 rows, 256 thr, warps laid 4(m) x 2(n-half).
// ---------------------------------------------------------------------------
__global__ __launch_bounds__(256) void qkv_kernel(
    const float* __restrict__ x,
    const float* __restrict__ Wq, const float* __restrict__ bq,
    const float* __restrict__ Wk, const float* __restrict__ bk,
    const float* __restrict__ Wv, const float* __restrict__ bv) {
  extern __shared__ uint32_t sm[];
  uint32_t* Xs = sm;               // 64*PAD
  uint32_t* Aq = Xs + 64 * PAD;
  uint32_t* Ak = Aq + 64 * PAD;
  uint32_t* Av = Ak + 64 * PAD;
  const int tid = threadIdx.x;
  const int rowbase = blockIdx.x * 64;

  for (int idx = tid; idx < 64 * 64; idx += 256) {
    int r = idx >> 6, d = idx & 63;
    Xs[r * PAD + d] = f2tf(x[(size_t)(rowbase + r) * 64 + d]);
    Aq[r * PAD + d] = f2tf(Wq[idx]);
    Ak[r * PAD + d] = f2tf(Wk[idx]);
    Av[r * PAD + d] = f2tf(Wv[idx]);
  }
  __syncthreads();

  const int wid = tid >> 5, lane = tid & 31;
  const int g = lane >> 2, t = lane & 3;
  const int wm = wid & 3, wn = wid >> 2;
  const int mrow = wm * 16;

  float cq[4][4] = {}, ck[4][4] = {}, cv[4][4] = {};
  for (int k0 = 0; k0 < 64; k0 += 8) {
    uint32_t a0 = Xs[(mrow + g) * PAD + k0 + t];
    uint32_t a1 = Xs[(mrow + g + 8) * PAD + k0 + t];
    uint32_t a2 = Xs[(mrow + g) * PAD + k0 + t + 4];
    uint32_t a3 = Xs[(mrow + g + 8) * PAD + k0 + t + 4];
#pragma unroll
    for (int nt = 0; nt < 4; nt++) {
      int n0 = wn * 32 + nt * 8;
      uint32_t b0 = Aq[(n0 + g) * PAD + k0 + t];
      uint32_t b1 = Aq[(n0 + g) * PAD + k0 + t + 4];
      mma_tf32(cq[nt], a0, a1, a2, a3, b0, b1);
      b0 = Ak[(n0 + g) * PAD + k0 + t];
      b1 = Ak[(n0 + g) * PAD + k0 + t + 4];
      mma_tf32(ck[nt], a0, a1, a2, a3, b0, b1);
      b0 = Av[(n0 + g) * PAD + k0 + t];
      b1 = Av[(n0 + g) * PAD + k0 + t + 4];
      mma_tf32(cv[nt], a0, a1, a2, a3, b0, b1);
    }
  }

#pragma unroll
  for (int nt = 0; nt < 4; nt++)
#pragma unroll
    for (int i = 0; i < 4; i++) {
      int row = rowbase + mrow + g + ((i >= 2) ? 8 : 0);
      int col = wn * 32 + nt * 8 + 2 * t + (i & 1);
      int b = row / (PS * PH);
      int rem = row - b * (PS * PH);
      int s = rem / PH;
      int h = rem - s * PH;
      size_t base = ((size_t)(b * PH + h) * PS + s) * PHD + col;
      g_Q[base] = cq[nt][i] + bq[col];
      g_K[base] = ck[nt][i] + bk[col];
      g_V[base] = cv[nt][i] + bv[col];
    }
}

// ---------------------------------------------------------------------------
// Kernel 2: causal flash attention, tf32 mma. Block = (b,h) x 128-query tile,
// 8 warps, each warp owns 16 query rows x all 64 cols -> warp-local softmax.
// ---------------------------------------------------------------------------
__global__ __launch_bounds__(256) void attn_kernel() {
  extern __shared__ uint32_t sm[];
  uint32_t* Qs = sm;                 // 128*PAD
  uint32_t* Ks = Qs + 128 * PAD;     // 64*PAD
  uint32_t* Vs = Ks + 64 * PAD;      // 64*PAD
  uint32_t* Ps = Vs + 64 * PAD;      // 128*PAD (warp-private rows)
  const int tid = threadIdx.x;
  const int wid = tid >> 5, lane = tid & 31;
  const int g = lane >> 2, t = lane & 3;
  const int mrow = wid * 16;
  const int bh = blockIdx.y;
  const int qi = (PS / 128 - 1) - blockIdx.x;  // big tiles first

  const float* Qg = g_Q + ((size_t)bh * PS + (size_t)qi * 128) * PHD;
  for (int idx = tid; idx < 128 * 64; idx += 256) {
    int r = idx >> 6, d = idx & 63;
    Qs[r * PAD + d] = f2tf(Qg[idx] * 0.125f);  // 1/sqrt(64) folded in
  }

  float m0 = -1e30f, m1 = -1e30f, l0 = 0.f, l1 = 0.f;
  float o[8][4] = {};
  const int qrow0 = qi * 128 + mrow + g;  // rows for regs {0,1}; +8 for {2,3}

  for (int j = 0; j <= 2 * qi + 1; j++) {
    __syncthreads();  // all warps done with Ks/Vs (and Qs loaded on j==0)
    const float* Kg = g_K + ((size_t)bh * PS + (size_t)j * 64) * PHD;
    const float* Vg = g_V + ((size_t)bh * PS + (size_t)j * 64) * PHD;
    for (int idx = tid; idx < 64 * 64; idx += 256) {
      int r = idx >> 6, d = idx & 63;
      Ks[r * PAD + d] = f2tf(Kg[idx]);
      Vs[r * PAD + d] = f2tf(Vg[idx]);
    }
    __syncthreads();

    // S = Q @ K^T
    float s[8][4] = {};
#pragma unroll
    for (int k0 = 0; k0 < 64; k0 += 8) {
      uint32_t a0 = Qs[(mrow + g) * PAD + k0 + t];
      uint32_t a1 = Qs[(mrow + g + 8) * PAD + k0 + t];
      uint32_t a2 = Qs[(mrow + g) * PAD + k0 + t + 4];
      uint32_t a3 = Qs[(mrow + g + 8) * PAD + k0 + t + 4];
#pragma unroll
      for (int nt = 0; nt < 8; nt++) {
        uint32_t b0 = Ks[(nt * 8 + g) * PAD + k0 + t];
        uint32_t b1 = Ks[(nt * 8 + g) * PAD + k0 + t + 4];
        mma_tf32(s[nt], a0, a1, a2, a3, b0, b1);
      }
    }

    if (j >= 2 * qi) {  // causal mask (only the top two key tiles can clip)
#pragma unroll
      for (int nt = 0; nt < 8; nt++)
#pragma unroll
        for (int i = 0; i < 4; i++) {
          int col = j * 64 + nt * 8 + 2 * t + (i & 1);
          int row = qrow0 + ((i >= 2) ? 8 : 0);
          if (col > row) s[nt][i] = -1e30f;
        }
    }

    // online softmax (rows warp-local; reduce over 4-lane quad)
    float rmax0 = -1e30f, rmax1 = -1e30f;
#pragma unroll
    for (int nt = 0; nt < 8; nt++) {
      rmax0 = fmaxf(rmax0, fmaxf(s[nt][0], s[nt][1]));
      rmax1 = fmaxf(rmax1, fmaxf(s[nt][2], s[nt][3]));
    }
    rmax0 = fmaxf(rmax0, __shfl_xor_sync(0xffffffffu, rmax0, 1));
    rmax0 = fmaxf(rmax0, __shfl_xor_sync(0xffffffffu, rmax0, 2));
    rmax1 = fmaxf(rmax1, __shfl_xor_sync(0xffffffffu, rmax1, 1));
    rmax1 = fmaxf(rmax1, __shfl_xor_sync(0xffffffffu, rmax1, 2));

    float nm0 = fmaxf(m0, rmax0), nm1 = fmaxf(m1, rmax1);
    float sc0 = __expf(m0 - nm0), sc1 = __expf(m1 - nm1);
    m0 = nm0;
    m1 = nm1;

    float rs0 = 0.f, rs1 = 0.f;
#pragma unroll
    for (int nt = 0; nt < 8; nt++) {
#pragma unroll
      for (int i = 0; i < 4; i++) {
        float nm = (i >= 2) ? nm1 : nm0;
        uint32_t u = f2tf(__expf(s[nt][i] - nm));
        float pf = __uint_as_float(u);  // tf32-rounded value; l matches P
        if (i >= 2) rs1 += pf; else rs0 += pf;
        Ps[(mrow + g + ((i >= 2) ? 8 : 0)) * PAD + nt * 8 + 2 * t + (i & 1)] = u;
      }
    }
    rs0 += __shfl_xor_sync(0xffffffffu, rs0, 1);
    rs0 += __shfl_xor_sync(0xffffffffu, rs0, 2);
    rs1 += __shfl_xor_sync(0xffffffffu, rs1, 1);
    rs1 += __shfl_xor_sync(0xffffffffu, rs1, 2);
    l0 = l0 * sc0 + rs0;
    l1 = l1 * sc1 + rs1;
#pragma unroll
    for (int nt = 0; nt < 8; nt++) {
      o[nt][0] *= sc0;
      o[nt][1] *= sc0;
      o[nt][2] *= sc1;
      o[nt][3] *= sc1;
    }

    __syncwarp();  // Ps rows are warp-private; order STS -> LDS within warp

    // O += P @ V
#pragma unroll
    for (int k0 = 0; k0 < 64; k0 += 8) {
      uint32_t a0 = Ps[(mrow + g) * PAD + k0 + t];
      uint32_t a1 = Ps[(mrow + g + 8) * PAD + k0 + t];
      uint32_t a2 = Ps[(mrow + g) * PAD + k0 + t + 4];
      uint32_t a3 = Ps[(mrow + g + 8) * PAD + k0 + t + 4];
#pragma unroll
      for (int nt = 0; nt < 8; nt++) {
        uint32_t b0 = Vs[(k0 + t) * PAD + nt * 8 + g];
        uint32_t b1 = Vs[(k0 + t + 4) * PAD + nt * 8 + g];
        mma_tf32(o[nt], a0, a1, a2, a3, b0, b1);
      }
    }
  }

  const int b = bh >> 4, h = bh & 15;
  float inv0 = 1.f / l0, inv1 = 1.f / l1;
#pragma unroll
  for (int nt = 0; nt < 8; nt++)
#pragma unroll
    for (int i = 0; i < 4; i++) {
      int srow = qi * 128 + mrow + g + ((i >= 2) ? 8 : 0);
      int col = nt * 8 + 2 * t + (i & 1);
      g_Y[((size_t)b * PS + srow) * PE + h * PHD + col] =
          o[nt][i] * ((i >= 2) ? inv1 : inv0);
    }
}

// ---------------------------------------------------------------------------
// Kernel 3: output projection (tf32 mma). out[4096,1024] = Y @ Wp^T + bp.
// Block: 128 rows x 64 cols, 8 warps each 16x64, K chunks of 64.
// ---------------------------------------------------------------------------
__global__ __launch_bounds__(256) void proj_kernel(
    const float* __restrict__ W, const float* __restrict__ bias,
    float* __restrict__ out) {
  extern __shared__ uint32_t sm[];
  uint32_t* Ys = sm;               // 128*PAD
  uint32_t* Ws = Ys + 128 * PAD;   // 64*PAD
  const int tid = threadIdx.x;
  const int wid = tid >> 5, lane = tid & 31;
  const int g = lane >> 2, t = lane & 3;
  const int mrow = wid * 16;
  const int bm = blockIdx.y, bn = blockIdx.x;

  float acc[8][4] = {};
  for (int kt = 0; kt < PE / 64; kt++) {
    __syncthreads();
    for (int idx = tid; idx < 128 * 64; idx += 256) {
      int r = idx >> 6, d = idx & 63;
      Ys[r * PAD + d] = f2tf(g_Y[(size_t)(bm * 128 + r) * PE + kt * 64 + d]);
    }
    for (int idx = tid; idx < 64 * 64; idx += 256) {
      int r = idx >> 6, d = idx & 63;
      Ws[r * PAD + d] = f2tf(W[(size_t)(bn * 64 + r) * PE + kt * 64 + d]);
    }
    __syncthreads();
#pragma unroll
    for (int k0 = 0; k0 < 64; k0 += 8) {
      uint32_t a0 = Ys[(mrow + g) * PAD + k0 + t];
      uint32_t a1 = Ys[(mrow + g + 8) * PAD + k0 + t];
      uint32_t a2 = Ys[(mrow + g) * PAD + k0 + t + 4];
      uint32_t a3 = Ys[(mrow + g + 8) * PAD + k0 + t + 4];
#pragma unroll
      for (int nt = 0; nt < 8; nt++) {
        uint32_t b0 = Ws[(nt * 8 + g) * PAD + k0 + t];
        uint32_t b1 = Ws[(nt * 8 + g) * PAD + k0 + t + 4];
        mma_tf32(acc[nt], a0, a1, a2, a3, b0, b1);
      }
    }
  }

#pragma unroll
  for (int nt = 0; nt < 8; nt++)
#pragma unroll
    for (int i = 0; i < 4; i++) {
      int row = bm * 128 + mrow + g + ((i >= 2) ? 8 : 0);
      int col = bn * 64 + nt * 8 + 2 * t + (i & 1);
      out[(size_t)row * PE + col] = acc[nt][i] + bias[col];
    }
}

// ---------------------------------------------------------------------------
extern "C" void kernel_launch(void* const* d_in, const int* in_sizes, int n_in,
                              void* d_out, int out_size) {
  const float* x  = (const float*)d_in[0];
  const float* Wq = (const float*)d_in[1];
  const float* bq = (const float*)d_in[2];
  const float* Wk = (const float*)d_in[3];
  const float* bk = (const float*)d_in[4];
  const float* Wv = (const float*)d_in[5];
  const float* bv = (const float*)d_in[6];
  const float* Wp = (const float*)d_in[7];
  const float* bp = (const float*)d_in[8];
  float* out = (float*)d_out;

  const int smem_qkv  = 4 * 64 * PAD * 4;          // 69,632 B
  const int smem_attn = (128 + 64 + 64 + 128) * PAD * 4;  // 104,448 B
  const int smem_proj = (128 + 64) * PAD * 4;      // 52,224 B
  cudaFuncSetAttribute(qkv_kernel, cudaFuncAttributeMaxDynamicSharedMemorySize, smem_qkv);
  cudaFuncSetAttribute(attn_kernel, cudaFuncAttributeMaxDynamicSharedMemorySize, smem_attn);
  cudaFuncSetAttribute(proj_kernel, cudaFuncAttributeMaxDynamicSharedMemorySize, smem_proj);

  qkv_kernel<<<MROWS / 64, 256, smem_qkv>>>(x, Wq, bq, Wk, bk, Wv, bv);
  attn_kernel<<<dim3(PS / 128, PB * PH), 256, smem_attn>>>();
  proj_kernel<<<dim3(PE / 64, (PB * PS) / 128), 256, smem_proj>>>(Wp, bp, out);
}

// round 3
// speedup vs baseline: 5.8813x; 1.3116x over previous
#include <cuda_runtime.h>
#include <cstdint>

#define PB 2
#define PS 2048
#define PE 1024
#define PH 16
#define PHD 64
#define MROWS (PB * PS * PH)
#define PAD 68   // 64-col tiles: (r*68 + c) mod 32 = 4r+c -> fragment loads conflict-free
#define PAD2 36  // 32-col tiles: same property

// Scratch, all tf32 bit patterns stored as uint32 (allocation-free rule)
__device__ uint32_t g_Q[(size_t)PB * PH * PS * PHD];
__device__ uint32_t g_K[(size_t)PB * PH * PS * PHD];
__device__ uint32_t g_V[(size_t)PB * PH * PS * PHD];
__device__ uint32_t g_Y[(size_t)PB * PS * PE];
__device__ uint32_t g_Wp[(size_t)PE * PE];
__device__ uint32_t g_Wq[PHD * PHD];
__device__ uint32_t g_Wk[PHD * PHD];
__device__ uint32_t g_Wv[PHD * PHD];

__device__ __forceinline__ uint32_t f2tf(float x) {
  uint32_t u;
  asm("cvt.rna.tf32.f32 %0, %1;" : "=r"(u) : "f"(x));
  return u;
}
__device__ __forceinline__ float ex2(float x) {
  float y;
  asm("ex2.approx.ftz.f32 %0, %1;" : "=f"(y) : "f"(x));
  return y;
}
__device__ __forceinline__ void mma_tf32(float c[4], uint32_t a0, uint32_t a1,
                                         uint32_t a2, uint32_t a3, uint32_t b0,
                                         uint32_t b1) {
  asm volatile(
      "mma.sync.aligned.m16n8k8.row.col.f32.tf32.tf32.f32 "
      "{%0,%1,%2,%3}, {%4,%5,%6,%7}, {%8,%9}, {%0,%1,%2,%3};"
      : "+f"(c[0]), "+f"(c[1]), "+f"(c[2]), "+f"(c[3])
      : "r"(a0), "r"(a1), "r"(a2), "r"(a3), "r"(b0), "r"(b1));
}
__device__ __forceinline__ void cpa16(uint32_t* smem_dst, const void* gsrc) {
  uint32_t d = (uint32_t)__cvta_generic_to_shared(smem_dst);
  asm volatile("cp.async.cg.shared.global [%0], [%1], 16;" ::"r"(d), "l"(gsrc));
}
__device__ __forceinline__ void cp_commit() {
  asm volatile("cp.async.commit_group;");
}
__device__ __forceinline__ void cp_wait1() {
  asm volatile("cp.async.wait_group 1;");
}
__device__ __forceinline__ void cp_wait0() {
  asm volatile("cp.async.wait_group 0;");
}

// ---------------------------------------------------------------------------
// Kernel 0: one-time tf32 pre-conversion of weights.
// ---------------------------------------------------------------------------
__global__ __launch_bounds__(256) void prep_kernel(
    const float* __restrict__ Wp, const float* __restrict__ Wq,
    const float* __restrict__ Wk, const float* __restrict__ Wv) {
  int i = blockIdx.x * 256 + threadIdx.x;
  if (i < PE * PE) g_Wp[i] = f2tf(Wp[i]);
  if (i < PHD * PHD) {
    g_Wq[i] = f2tf(Wq[i]);
    g_Wk[i] = f2tf(Wk[i]);
    g_Wv[i] = f2tf(Wv[i]);
  }
}

// ---------------------------------------------------------------------------
// Kernel 1: fused QKV projection. 512 thr, 128 rows/block.
// Q output pre-scaled by (1/sqrt(64))*log2(e) so attention uses ex2 directly.
// ---------------------------------------------------------------------------
__global__ __launch_bounds__(512) void qkv_kernel(
    const float* __restrict__ x, const float* __restrict__ bq,
    const float* __restrict__ bk, const float* __restrict__ bv) {
  extern __shared__ uint32_t sm[];
  uint32_t* Xs = sm;               // 128*PAD
  uint32_t* Aq = Xs + 128 * PAD;   // 64*PAD each
  uint32_t* Ak = Aq + 64 * PAD;
  uint32_t* Av = Ak + 64 * PAD;
  const int tid = threadIdx.x;
  const int rowbase = blockIdx.x * 128;

  // Weights: already tf32, stream with cp.async (1024 f4 each over 512 thr)
#pragma unroll
  for (int r = 0; r < 2; r++) {
    int f = tid + 512 * r;
    int row = f >> 4, col = (f & 15) * 4;
    cpa16(&Aq[row * PAD + col], &g_Wq[row * 64 + col]);
    cpa16(&Ak[row * PAD + col], &g_Wk[row * 64 + col]);
    cpa16(&Av[row * PAD + col], &g_Wv[row * 64 + col]);
  }
  cp_commit();
  // x: fp32 -> tf32 on the way in
#pragma unroll
  for (int r = 0; r < 4; r++) {
    int f = tid + 512 * r;
    int row = f >> 4, col = (f & 15) * 4;
    float4 v = *(const float4*)&x[(size_t)(rowbase + row) * 64 + col];
    uint4 u = {f2tf(v.x), f2tf(v.y), f2tf(v.z), f2tf(v.w)};
    *(uint4*)&Xs[row * PAD + col] = u;
  }
  cp_wait0();
  __syncthreads();

  const int wid = tid >> 5, lane = tid & 31;
  const int g = lane >> 2, t = lane & 3;
  const int mrow = (wid & 7) * 16;
  const int wn = wid >> 3;

  float cq[4][4] = {}, ck[4][4] = {}, cv[4][4] = {};
#pragma unroll
  for (int k0 = 0; k0 < 64; k0 += 8) {
    uint32_t a0 = Xs[(mrow + g) * PAD + k0 + t];
    uint32_t a1 = Xs[(mrow + g + 8) * PAD + k0 + t];
    uint32_t a2 = Xs[(mrow + g) * PAD + k0 + t + 4];
    uint32_t a3 = Xs[(mrow + g + 8) * PAD + k0 + t + 4];
#pragma unroll
    for (int nt = 0; nt < 4; nt++) {
      int n0 = wn * 32 + nt * 8;
      mma_tf32(cq[nt], a0, a1, a2, a3, Aq[(n0 + g) * PAD + k0 + t],
               Aq[(n0 + g) * PAD + k0 + t + 4]);
      mma_tf32(ck[nt], a0, a1, a2, a3, Ak[(n0 + g) * PAD + k0 + t],
               Ak[(n0 + g) * PAD + k0 + t + 4]);
      mma_tf32(cv[nt], a0, a1, a2, a3, Av[(n0 + g) * PAD + k0 + t],
               Av[(n0 + g) * PAD + k0 + t + 4]);
    }
  }

  const float qscale = 0.125f * 1.4426950408889634f;  // 1/sqrt(64) * log2(e)
#pragma unroll
  for (int nt = 0; nt < 4; nt++)
#pragma unroll
    for (int i = 0; i < 4; i++) {
      int row = rowbase + mrow + g + ((i >= 2) ? 8 : 0);
      int col = wn * 32 + nt * 8 + 2 * t + (i & 1);
      int b = row >> 15;              // row / (S*H)
      int s = (row >> 4) & (PS - 1);  // (row / H) % S
      int h = row & 15;
      size_t base = ((size_t)(b * PH + h) * PS + s) * PHD + col;
      g_Q[base] = f2tf((cq[nt][i] + bq[col]) * qscale);
      g_K[base] = f2tf(ck[nt][i] + bk[col]);
      g_V[base] = f2tf(cv[nt][i] + bv[col]);
    }
}

// ---------------------------------------------------------------------------
// Kernel 2: causal flash attention, 256 thr, 128 queries/block, 32-row KV
// stages double-buffered with cp.async. Softmax in log2 domain (ex2).
// ---------------------------------------------------------------------------
__global__ __launch_bounds__(256) void attn_kernel() {
  extern __shared__ uint32_t sm[];
  uint32_t* Qs = sm;                     // 128*PAD
  uint32_t* Ks = Qs + 128 * PAD;         // 2 bufs x 32*PAD
  uint32_t* Vs = Ks + 2 * 32 * PAD;      // 2 bufs x 32*PAD
  uint32_t* Ps = Vs + 2 * 32 * PAD;      // 128*PAD2
  const int tid = threadIdx.x;
  const int wid = tid >> 5, lane = tid & 31;
  const int g = lane >> 2, t = lane & 3;
  const int mrow = wid * 16;
  const int bh = blockIdx.y;
  const int qi = (PS / 128 - 1) - blockIdx.x;  // big tiles first
  const int ntiles = 4 * qi + 4;

  const uint32_t* Qg = g_Q + ((size_t)bh * PS + (size_t)qi * 128) * PHD;
  const uint32_t* Kg = g_K + (size_t)bh * PS * PHD;
  const uint32_t* Vg = g_V + (size_t)bh * PS * PHD;

  // Prologue group: Q tile + KV stage 0
#pragma unroll
  for (int r = 0; r < 8; r++) {
    int f = tid + 256 * r;
    int row = f >> 4, col = (f & 15) * 4;
    cpa16(&Qs[row * PAD + col], &Qg[row * 64 + col]);
  }
#pragma unroll
  for (int r = 0; r < 2; r++) {
    int f = tid + 256 * r;
    int row = f >> 4, col = (f & 15) * 4;
    cpa16(&Ks[row * PAD + col], &Kg[row * 64 + col]);
    cpa16(&Vs[row * PAD + col], &Vg[row * 64 + col]);
  }
  cp_commit();

  float m0 = -1e30f, m1 = -1e30f, l0 = 0.f, l1 = 0.f;
  float o[8][4] = {};
  const int qrow0 = qi * 128 + mrow + g;

  for (int j = 0; j < ntiles; j++) {
    const int buf = j & 1;
    if (j + 1 < ntiles) {
      const int nb = (j + 1) & 1;
      const uint32_t* Kn = Kg + (size_t)(j + 1) * 32 * 64;
      const uint32_t* Vn = Vg + (size_t)(j + 1) * 32 * 64;
#pragma unroll
      for (int r = 0; r < 2; r++) {
        int f = tid + 256 * r;
        int row = f >> 4, col = (f & 15) * 4;
        cpa16(&Ks[(nb * 32 + row) * PAD + col], &Kn[row * 64 + col]);
        cpa16(&Vs[(nb * 32 + row) * PAD + col], &Vn[row * 64 + col]);
      }
      cp_commit();
      cp_wait1();
    } else {
      cp_wait0();
    }
    __syncthreads();  // stage j visible to all; all done with buf from j-1

    const uint32_t* Kb = Ks + buf * 32 * PAD;
    const uint32_t* Vb = Vs + buf * 32 * PAD;

    // S = Q @ K^T  (128 x 32 chunk)
    float s[4][4] = {};
#pragma unroll
    for (int k0 = 0; k0 < 64; k0 += 8) {
      uint32_t a0 = Qs[(mrow + g) * PAD + k0 + t];
      uint32_t a1 = Qs[(mrow + g + 8) * PAD + k0 + t];
      uint32_t a2 = Qs[(mrow + g) * PAD + k0 + t + 4];
      uint32_t a3 = Qs[(mrow + g + 8) * PAD + k0 + t + 4];
#pragma unroll
      for (int nt = 0; nt < 4; nt++) {
        mma_tf32(s[nt], a0, a1, a2, a3, Kb[(nt * 8 + g) * PAD + k0 + t],
                 Kb[(nt * 8 + g) * PAD + k0 + t + 4]);
      }
    }

    if (j >= 4 * qi) {  // only the 4 diagonal-band tiles can clip
#pragma unroll
      for (int nt = 0; nt < 4; nt++)
#pragma unroll
        for (int i = 0; i < 4; i++) {
          int col = j * 32 + nt * 8 + 2 * t + (i & 1);
          int row = qrow0 + ((i >= 2) ? 8 : 0);
          if (col > row) s[nt][i] = -1e30f;
        }
    }

    // online softmax (log2 domain), rows warp-local, quad reduce
    float rmax0 = -1e30f, rmax1 = -1e30f;
#pragma unroll
    for (int nt = 0; nt < 4; nt++) {
      rmax0 = fmaxf(rmax0, fmaxf(s[nt][0], s[nt][1]));
      rmax1 = fmaxf(rmax1, fmaxf(s[nt][2], s[nt][3]));
    }
    rmax0 = fmaxf(rmax0, __shfl_xor_sync(0xffffffffu, rmax0, 1));
    rmax0 = fmaxf(rmax0, __shfl_xor_sync(0xffffffffu, rmax0, 2));
    rmax1 = fmaxf(rmax1, __shfl_xor_sync(0xffffffffu, rmax1, 1));
    rmax1 = fmaxf(rmax1, __shfl_xor_sync(0xffffffffu, rmax1, 2));

    float nm0 = fmaxf(m0, rmax0), nm1 = fmaxf(m1, rmax1);
    float sc0 = ex2(m0 - nm0), sc1 = ex2(m1 - nm1);
    m0 = nm0;
    m1 = nm1;

    float rs0 = 0.f, rs1 = 0.f;
#pragma unroll
    for (int nt = 0; nt < 4; nt++)
#pragma unroll
      for (int i = 0; i < 4; i++) {
        float nm = (i >= 2) ? nm1 : nm0;
        uint32_t u = f2tf(ex2(s[nt][i] - nm));
        float pf = __uint_as_float(u);  // l matches tf32-rounded P exactly
        if (i >= 2) rs1 += pf; else rs0 += pf;
        Ps[(mrow + g + ((i >= 2) ? 8 : 0)) * PAD2 + nt * 8 + 2 * t + (i & 1)] = u;
      }
    rs0 += __shfl_xor_sync(0xffffffffu, rs0, 1);
    rs0 += __shfl_xor_sync(0xffffffffu, rs0, 2);
    rs1 += __shfl_xor_sync(0xffffffffu, rs1, 1);
    rs1 += __shfl_xor_sync(0xffffffffu, rs1, 2);
    l0 = l0 * sc0 + rs0;
    l1 = l1 * sc1 + rs1;
#pragma unroll
    for (int nt = 0; nt < 8; nt++) {
      o[nt][0] *= sc0;
      o[nt][1] *= sc0;
      o[nt][2] *= sc1;
      o[nt][3] *= sc1;
    }

    __syncwarp();  // Ps rows are warp-private; order STS before LDS

    // O += P @ V  (128x32 @ 32x64)
#pragma unroll
    for (int k0 = 0; k0 < 32; k0 += 8) {
      uint32_t a0 = Ps[(mrow + g) * PAD2 + k0 + t];
      uint32_t a1 = Ps[(mrow + g + 8) * PAD2 + k0 + t];
      uint32_t a2 = Ps[(mrow + g) * PAD2 + k0 + t + 4];
      uint32_t a3 = Ps[(mrow + g + 8) * PAD2 + k0 + t + 4];
#pragma unroll
      for (int nt = 0; nt < 8; nt++) {
        mma_tf32(o[nt], a0, a1, a2, a3, Vb[(k0 + t) * PAD + nt * 8 + g],
                 Vb[(k0 + t + 4) * PAD + nt * 8 + g]);
      }
    }
    __syncthreads();  // all warps done with buf before it is refilled at j+1
  }

  const int b = bh >> 4, h = bh & 15;
  float inv0 = 1.f / l0, inv1 = 1.f / l1;
#pragma unroll
  for (int nt = 0; nt < 8; nt++)
#pragma unroll
    for (int i = 0; i < 4; i++) {
      int srow = qi * 128 + mrow + g + ((i >= 2) ? 8 : 0);
      int col = nt * 8 + 2 * t + (i & 1);
      g_Y[((size_t)b * PS + srow) * PE + h * PHD + col] =
          f2tf(o[nt][i] * ((i >= 2) ? inv1 : inv0));
    }
}

// ---------------------------------------------------------------------------
// Kernel 3: output projection. 128x128 tile/block, 32-deep K stages,
// cp.async double-buffered. All inputs pre-converted tf32.
// ---------------------------------------------------------------------------
__global__ __launch_bounds__(256) void proj_kernel(
    const float* __restrict__ bias, float* __restrict__ out) {
  extern __shared__ uint32_t sm[];
  uint32_t* Ys = sm;                  // 2 bufs x 128*PAD2
  uint32_t* Ws = Ys + 2 * 128 * PAD2; // 2 bufs x 128*PAD2
  const int tid = threadIdx.x;
  const int wid = tid >> 5, lane = tid & 31;
  const int g = lane >> 2, t = lane & 3;
  const int mrow = wid * 16;
  const int bm = blockIdx.y, bn = blockIdx.x;

  const uint32_t* Yg = g_Y + (size_t)bm * 128 * PE;
  const uint32_t* Wg = g_Wp + (size_t)bn * 128 * PE;

  // Prologue: stage 0
#pragma unroll
  for (int r = 0; r < 4; r++) {
    int f = tid + 256 * r;
    int row = f >> 3, col = (f & 7) * 4;
    cpa16(&Ys[row * PAD2 + col], &Yg[(size_t)row * PE + col]);
    cpa16(&Ws[row * PAD2 + col], &Wg[(size_t)row * PE + col]);
  }
  cp_commit();

  float acc[16][4] = {};
  const int NK = PE / 32;
  for (int kt = 0; kt < NK; kt++) {
    const int buf = kt & 1;
    if (kt + 1 < NK) {
      const int nb = (kt + 1) & 1;
      const uint32_t* Yn = Yg + (size_t)(kt + 1) * 32;
      const uint32_t* Wn = Wg + (size_t)(kt + 1) * 32;
#pragma unroll
      for (int r = 0; r < 4; r++) {
        int f = tid + 256 * r;
        int row = f >> 3, col = (f & 7) * 4;
        cpa16(&Ys[(nb * 128 + row) * PAD2 + col], &Yn[(size_t)row * PE + col]);
        cpa16(&Ws[(nb * 128 + row) * PAD2 + col], &Wn[(size_t)row * PE + col]);
      }
      cp_commit();
      cp_wait1();
    } else {
      cp_wait0();
    }
    __syncthreads();

    const uint32_t* Yb = Ys + buf * 128 * PAD2;
    const uint32_t* Wb = Ws + buf * 128 * PAD2;
#pragma unroll
    for (int k0 = 0; k0 < 32; k0 += 8) {
      uint32_t a0 = Yb[(mrow + g) * PAD2 + k0 + t];
      uint32_t a1 = Yb[(mrow + g + 8) * PAD2 + k0 + t];
      uint32_t a2 = Yb[(mrow + g) * PAD2 + k0 + t + 4];
      uint32_t a3 = Yb[(mrow + g + 8) * PAD2 + k0 + t + 4];
#pragma unroll
      for (int nt = 0; nt < 16; nt++) {
        mma_tf32(acc[nt], a0, a1, a2, a3, Wb[(nt * 8 + g) * PAD2 + k0 + t],
                 Wb[(nt * 8 + g) * PAD2 + k0 + t + 4]);
      }
    }
    __syncthreads();
  }

#pragma unroll
  for (int nt = 0; nt < 16; nt++)
#pragma unroll
    for (int i = 0; i < 4; i++) {
      int row = bm * 128 + mrow + g + ((i >= 2) ? 8 : 0);
      int col = bn * 128 + nt * 8 + 2 * t + (i & 1);
      out[(size_t)row * PE + col] = acc[nt][i] + bias[col];
    }
}

// ---------------------------------------------------------------------------
extern "C" void kernel_launch(void* const* d_in, const int* in_sizes, int n_in,
                              void* d_out, int out_size) {
  const float* x  = (const float*)d_in[0];
  const float* Wq = (const float*)d_in[1];
  const float* bq = (const float*)d_in[2];
  const float* Wk = (const float*)d_in[3];
  const float* bk = (const float*)d_in[4];
  const float* Wv = (const float*)d_in[5];
  const float* bv = (const float*)d_in[6];
  const float* Wp = (const float*)d_in[7];
  const float* bp = (const float*)d_in[8];
  float* out = (float*)d_out;

  const int smem_qkv  = (128 + 3 * 64) * PAD * 4;                 // 87,040 B
  const int smem_attn = (128 * PAD + 128 * PAD + 128 * PAD2) * 4; // 88,064 B
  const int smem_proj = (4 * 128 * PAD2) * 4;                     // 73,728 B
  cudaFuncSetAttribute(qkv_kernel, cudaFuncAttributeMaxDynamicSharedMemorySize, smem_qkv);
  cudaFuncSetAttribute(attn_kernel, cudaFuncAttributeMaxDynamicSharedMemorySize, smem_attn);
  cudaFuncSetAttribute(proj_kernel, cudaFuncAttributeMaxDynamicSharedMemorySize, smem_proj);

  prep_kernel<<<(PE * PE + 255) / 256, 256>>>(Wp, Wq, Wk, Wv);
  qkv_kernel<<<MROWS / 128, 512, smem_qkv>>>(x, bq, bk, bv);
  attn_kernel<<<dim3(PS / 128, PB * PH), 256, smem_attn>>>();
  proj_kernel<<<dim3(PE / 128, (PB * PS) / 128), 256, smem_proj>>>(bp, out);
}